// round 14
// baseline (speedup 1.0000x reference)
#include <cuda_runtime.h>
#include <cuda_bf16.h>
#include <math.h>
#include <stdint.h>

// Fixed shapes: x[16,2048,128], adj[16,2048,2048], W[128,128], bias[1,128]
#define B_DIM 16
#define N_DIM 2048
#define F_DIM 128
#define NEG_BIG (-9e15f)
#define NELEM ((size_t)B_DIM * N_DIM * F_DIM)   // 4194304

// ---------------- device scratch (no allocation allowed) -------------------
__device__ __align__(256) __nv_bfloat16 g_x_h [NELEM];
__device__ __align__(256) __nv_bfloat16 g_x_l [NELEM];
__device__ __align__(256) __nv_bfloat16 g_wt_h[F_DIM * F_DIM];   // W^T [g][f]
__device__ __align__(256) __nv_bfloat16 g_wt_l[F_DIM * F_DIM];

// ---------------- PTX helpers (sm_80+ features only) ------------------------
__device__ __forceinline__ uint32_t smem_u32(const void* p) {
    uint32_t a;
    asm("{ .reg .u64 t; cvta.to.shared.u64 t, %1; cvt.u32.u64 %0, t; }"
        : "=r"(a) : "l"(p));
    return a;
}
__device__ __forceinline__ void cp16(uint32_t saddr, const void* gaddr) {
    asm volatile("cp.async.cg.shared.global [%0], [%1], 16;"
                 :: "r"(saddr), "l"(gaddr));
}
#define CP_COMMIT() asm volatile("cp.async.commit_group;" ::: "memory")
#define CP_WAIT1()  asm volatile("cp.async.wait_group 1;"  ::: "memory")
#define CP_WAIT0()  asm volatile("cp.async.wait_group 0;"  ::: "memory")

__device__ __forceinline__ void ldsm4(uint32_t* r, uint32_t addr) {
    asm volatile("ldmatrix.sync.aligned.m8n8.x4.shared.b16 {%0,%1,%2,%3}, [%4];"
                 : "=r"(r[0]), "=r"(r[1]), "=r"(r[2]), "=r"(r[3]) : "r"(addr));
}
__device__ __forceinline__ void ldsm4t(uint32_t* r, uint32_t addr) {
    asm volatile("ldmatrix.sync.aligned.m8n8.x4.trans.shared.b16 {%0,%1,%2,%3}, [%4];"
                 : "=r"(r[0]), "=r"(r[1]), "=r"(r[2]), "=r"(r[3]) : "r"(addr));
}
// D += A*B  (m16n8k16, row.col, bf16 in, f32 accum)
__device__ __forceinline__ void mma16816(float* d, const uint32_t* a, const uint32_t* b) {
    asm volatile("mma.sync.aligned.m16n8k16.row.col.f32.bf16.bf16.f32 "
        "{%0,%1,%2,%3}, {%4,%5,%6,%7}, {%8,%9}, {%0,%1,%2,%3};"
        : "+f"(d[0]), "+f"(d[1]), "+f"(d[2]), "+f"(d[3])
        : "r"(a[0]), "r"(a[1]), "r"(a[2]), "r"(a[3]), "r"(b[0]), "r"(b[1]));
}

// packed bf16 hi/lo split of a float pair
__device__ __forceinline__ void split2(float a, float b, uint32_t& hi, uint32_t& lo) {
    uint32_t h;
    asm("cvt.rn.bf16x2.f32 %0, %1, %2;" : "=r"(h) : "f"(b), "f"(a));
    float ha = __uint_as_float(h << 16);
    float hb = __uint_as_float(h & 0xffff0000u);
    float la = a - ha, lb = b - hb;
    uint32_t l;
    asm("cvt.rn.bf16x2.f32 %0, %1, %2;" : "=r"(l) : "f"(lb), "f"(la));
    hi = h; lo = l;
}

// ---------------- SMEM layout (96KB total -> 2 blocks/SM) -------------------
// regions: 64 rows x 128 bf16 = 16KB; hi at +0, lo at +THB within a region.
// row = 256B = 16x 16B units, unit swizzle u ^= (row & 7).
#define THB      16384
#define SM_XW    0                           // 32KB: xw hi/lo (prologue: x rows)
#define SM_XB(buf) (32768 + (buf) * 32768)   // 2 x 32KB x-tile buffers
#define SM_TOTAL 98304

// ---------------------------------------------------------------------------
// Fused prep: x bf16 hi/lo split; first 16 blocks also split W^T.
// ---------------------------------------------------------------------------
__global__ void __launch_bounds__(256) split_kernel(const float* __restrict__ x,
                                                    const float* __restrict__ W)
{
    size_t i4 = (size_t)blockIdx.x * 256 + threadIdx.x;
    float4 v = *reinterpret_cast<const float4*>(x + i4 * 4);
    uint2 h, l;
    split2(v.x, v.y, h.x, l.x);
    split2(v.z, v.w, h.y, l.y);
    reinterpret_cast<uint2*>(g_x_h)[i4] = h;
    reinterpret_cast<uint2*>(g_x_l)[i4] = l;

    if (blockIdx.x < 16) {
        int idx0 = (blockIdx.x * 256 + threadIdx.x) * 4;
        #pragma unroll
        for (int k = 0; k < 4; k++) {
            int idx = idx0 + k;                    // 0..16383
            int gg = idx >> 7, f = idx & 127;
            float wv = W[f * F_DIM + gg];
            __nv_bfloat16 hh = __float2bfloat16(wv);
            __nv_bfloat16 ll = __float2bfloat16(wv - __bfloat162float(hh));
            g_wt_h[idx] = hh;                      // [g][f] row-major
            g_wt_l[idx] = ll;
        }
    }
}

// ---------------------------------------------------------------------------
// Main fused kernel. Block = 64-row tile of one batch, 4 warps (128 thr),
// 64-col kv tiles (32 iterations). 2 blocks/SM. Adjacency loaded directly
// per-fragment (no ballots): thread owns rows g,g+8 x cols 8nt+2t4(+1).
// ---------------------------------------------------------------------------
__global__ void __launch_bounds__(128, 2) gat_mma_kernel(
    const int*   __restrict__ adj,
    const float* __restrict__ bias,
    float*       __restrict__ out)
{
    extern __shared__ char sm[];
    const uint32_t sb = smem_u32(sm);

    const int b    = blockIdx.y;
    const int row0 = blockIdx.x * 64;
    const int tid  = threadIdx.x;
    const int lane = tid & 31;
    const int w    = tid >> 5;         // 0..3
    const int g    = lane >> 2;        // mma group row
    const int t4   = lane & 3;         // mma group col
    const int wrow0 = w * 16;          // warp's row base within 64-row tile
    const int mat  = lane >> 3;        // ldmatrix lane roles
    const int rr   = lane & 7;

    const char* xh_g  = (const char*)(g_x_h + (size_t)b * N_DIM * F_DIM);
    const char* xl_g  = (const char*)(g_x_l + (size_t)b * N_DIM * F_DIM);
    const char* xh_r0 = xh_g + (size_t)row0 * 256;   // this block's own rows
    const char* xl_r0 = xl_g + (size_t)row0 * 256;
    const int*  adjb  = adj + (size_t)b * N_DIM * N_DIM + (size_t)row0 * N_DIM;
    // per-thread adjacency row bases (rows g and g+8 of this warp)
    const int* adjr0 = adjb + (size_t)(wrow0 + g) * N_DIM + 2 * t4;
    const int* adjr1 = adjb + (size_t)(wrow0 + g + 8) * N_DIM + 2 * t4;

    // ======== prologue: compute xw tile (64 rows) via HMMA ========
    // x rows (A) -> SM_XW region; W^T (B, 128 rows) -> XB(0)+XB(1)
    #pragma unroll
    for (int k = 0; k < 8; k++) {              // 64 rows x 16 units
        int uu  = k * 128 + tid;
        int row = uu >> 4, u = uu & 15;
        uint32_t so = (uint32_t)row * 256 + ((u ^ (row & 7)) << 4);
        size_t   go = (size_t)row * 256 + u * 16;
        cp16(sb + SM_XW + so,       xh_r0 + go);
        cp16(sb + SM_XW + THB + so, xl_r0 + go);
    }
    #pragma unroll
    for (int k = 0; k < 16; k++) {             // 128 Wt rows x 16 units
        int uu  = k * 128 + tid;
        int row = uu >> 4, u = uu & 15;
        uint32_t so = SM_XB(row >> 6) + (uint32_t)(row & 63) * 256
                    + (((u ^ (row & 7))) << 4);
        size_t   go = (size_t)row * 256 + u * 16;
        cp16(sb + so,       (const char*)g_wt_h + go);
        cp16(sb + so + THB, (const char*)g_wt_l + go);
    }
    CP_COMMIT();
    CP_WAIT0();
    __syncthreads();

    {
        float cw[16][4];
        #pragma unroll
        for (int nt = 0; nt < 16; nt++)
            #pragma unroll
            for (int q = 0; q < 4; q++) cw[nt][q] = 0.f;

        #pragma unroll
        for (int s = 0; s < 8; s++) {
            int arow = wrow0 + rr + ((mat & 1) << 3);
            int au   = 2 * s + (mat >> 1);
            uint32_t aaddr = sb + SM_XW + (uint32_t)arow * 256 + ((au ^ (arow & 7)) << 4);
            uint32_t ah[4], al[4];
            ldsm4(ah, aaddr);
            ldsm4(al, aaddr + THB);
            #pragma unroll
            for (int np = 0; np < 16; np += 2) {
                int bu = 2 * s + (mat & 1);
                int br = np * 8 + rr + ((mat >> 1) << 3);
                uint32_t ba = sb + SM_XB(br >> 6) + (uint32_t)(br & 63) * 256
                            + ((bu ^ (br & 7)) << 4);
                uint32_t bh[4], bl[4];
                ldsm4(bh, ba);
                ldsm4(bl, ba + THB);
                mma16816(cw[np],     ah, &bh[0]);
                mma16816(cw[np],     ah, &bl[0]);
                mma16816(cw[np],     al, &bh[0]);
                mma16816(cw[np + 1], ah, &bh[2]);
                mma16816(cw[np + 1], ah, &bl[2]);
                mma16816(cw[np + 1], al, &bh[2]);
            }
        }

        __syncthreads();      // all reads of SM_XW (x rows) complete
        // split C-frags -> xw hi/lo smem tiles (overwrite SM_XW region)
        const int r0a = wrow0 + g, r1a = r0a + 8;
        #pragma unroll
        for (int nt = 0; nt < 16; nt++) {
            uint32_t h01, l01, h23, l23;
            split2(cw[nt][0], cw[nt][1], h01, l01);
            split2(cw[nt][2], cw[nt][3], h23, l23);
            uint32_t off0 = (uint32_t)r0a * 256 + ((nt ^ (r0a & 7)) << 4) + 4 * t4;
            uint32_t off1 = (uint32_t)r1a * 256 + ((nt ^ (r1a & 7)) << 4) + 4 * t4;
            *reinterpret_cast<uint32_t*>(sm + SM_XW + off0) = h01;
            *reinterpret_cast<uint32_t*>(sm + SM_XW + THB + off0) = l01;
            *reinterpret_cast<uint32_t*>(sm + SM_XW + off1) = h23;
            *reinterpret_cast<uint32_t*>(sm + SM_XW + THB + off1) = l23;
        }
    }
    __syncthreads();          // xw visible; XB reads done everywhere

    // prefetch x kv-tile 0 into XB(0)
    #pragma unroll
    for (int k = 0; k < 8; k++) {
        int uu  = k * 128 + tid;
        int row = uu >> 4, u = uu & 15;
        uint32_t so = (uint32_t)row * 256 + ((u ^ (row & 7)) << 4);
        size_t   go = (size_t)row * 256 + u * 16;
        cp16(sb + SM_XB(0) + so,       xh_g + go);
        cp16(sb + SM_XB(0) + THB + so, xl_g + go);
    }
    CP_COMMIT();

    float o[16][4];
    #pragma unroll
    for (int nt = 0; nt < 16; nt++)
        #pragma unroll
        for (int q = 0; q < 4; q++) o[nt][q] = 0.f;
    float m0r = -INFINITY, m1r = -INFINITY, l0r = 0.f, l1r = 0.f;

    for (int t = 0; t < 32; t++) {
        const int mbase = t * 64;

        // ---- fragment-aligned adj prefetch: 16 int2 per thread (no ballots)
        int2 aj0[8], aj1[8];
        #pragma unroll
        for (int nt = 0; nt < 8; nt++) {
            aj0[nt] = *reinterpret_cast<const int2*>(&adjr0[mbase + nt * 8]);
            aj1[nt] = *reinterpret_cast<const int2*>(&adjr1[mbase + nt * 8]);
        }

        __syncthreads();               // buf (t+1)&1 readers (tile t-1) done
        if (t < 31) {                  // prefetch next x tile into buf^1
            const char* nh = xh_g + (size_t)(t + 1) * 64 * 256;
            const char* nl = xl_g + (size_t)(t + 1) * 64 * 256;
            uint32_t dst = sb + SM_XB((t + 1) & 1);
            #pragma unroll
            for (int k = 0; k < 8; k++) {
                int uu = k * 128 + tid;
                int row = uu >> 4, u = uu & 15;
                uint32_t so = (uint32_t)row * 256 + ((u ^ (row & 7)) << 4);
                size_t   go = (size_t)row * 256 + u * 16;
                cp16(dst + so,       nh + go);
                cp16(dst + THB + so, nl + go);
            }
            CP_COMMIT();
            CP_WAIT1();
        } else {
            CP_WAIT0();
        }
        __syncthreads();               // current tile visible to all

        const uint32_t xb = sb + SM_XB(t & 1);   // x_h base; x_l = +THB

        // ---- S-GEMM: c[8][4] (16 rows x 64 cols), 3 bf16 terms, k = f (128)
        float c[8][4];
        #pragma unroll
        for (int nt = 0; nt < 8; nt++)
            #pragma unroll
            for (int q = 0; q < 4; q++) c[nt][q] = 0.f;

        #pragma unroll
        for (int s = 0; s < 8; s++) {
            int arow = wrow0 + rr + ((mat & 1) << 3);
            int au   = 2 * s + (mat >> 1);
            uint32_t aaddr = sb + SM_XW + (uint32_t)arow * 256 + ((au ^ (arow & 7)) << 4);
            uint32_t ah[4], al[4];
            ldsm4(ah, aaddr);
            ldsm4(al, aaddr + THB);
            #pragma unroll
            for (int np = 0; np < 4; np++) {
                int brow = np * 16 + rr + ((mat >> 1) << 3);
                int bu   = 2 * s + (mat & 1);
                uint32_t baddr = xb + (uint32_t)brow * 256 + ((bu ^ (brow & 7)) << 4);
                uint32_t bh[4], bl[4];
                ldsm4(bh, baddr);
                ldsm4(bl, baddr + THB);
                mma16816(c[2 * np],     ah, &bh[0]);
                mma16816(c[2 * np],     ah, &bl[0]);
                mma16816(c[2 * np],     al, &bh[0]);
                mma16816(c[2 * np + 1], ah, &bh[2]);
                mma16816(c[2 * np + 1], ah, &bl[2]);
                mma16816(c[2 * np + 1], al, &bh[2]);
            }
        }

        // ---- leakyrelu + direct adjacency mask + online softmax
        float rmax0 = -INFINITY, rmax1 = -INFINITY;
        #pragma unroll
        for (int nt = 0; nt < 8; nt++) {
            float e;
            e = fmaxf(c[nt][0], 0.1f * c[nt][0]);
            e = (aj0[nt].x > 0) ? e : NEG_BIG; c[nt][0] = e; rmax0 = fmaxf(rmax0, e);
            e = fmaxf(c[nt][1], 0.1f * c[nt][1]);
            e = (aj0[nt].y > 0) ? e : NEG_BIG; c[nt][1] = e; rmax0 = fmaxf(rmax0, e);
            e = fmaxf(c[nt][2], 0.1f * c[nt][2]);
            e = (aj1[nt].x > 0) ? e : NEG_BIG; c[nt][2] = e; rmax1 = fmaxf(rmax1, e);
            e = fmaxf(c[nt][3], 0.1f * c[nt][3]);
            e = (aj1[nt].y > 0) ? e : NEG_BIG; c[nt][3] = e; rmax1 = fmaxf(rmax1, e);
        }
        rmax0 = fmaxf(rmax0, __shfl_xor_sync(0xffffffffu, rmax0, 1));
        rmax0 = fmaxf(rmax0, __shfl_xor_sync(0xffffffffu, rmax0, 2));
        rmax1 = fmaxf(rmax1, __shfl_xor_sync(0xffffffffu, rmax1, 1));
        rmax1 = fmaxf(rmax1, __shfl_xor_sync(0xffffffffu, rmax1, 2));

        float nm0 = fmaxf(m0r, rmax0), nm1 = fmaxf(m1r, rmax1);
        float sc0 = (nm0 == -INFINITY) ? 0.f : __expf(m0r - nm0);
        float sc1 = (nm1 == -INFINITY) ? 0.f : __expf(m1r - nm1);
        m0r = nm0; m1r = nm1;

        float rs0 = 0.f, rs1 = 0.f;
        #pragma unroll
        for (int nt = 0; nt < 8; nt++) {         // c becomes P in place
            float p0 = __expf(c[nt][0] - nm0);   // masked NEG_BIG -> 0
            float p1 = __expf(c[nt][1] - nm0);
            float p2 = __expf(c[nt][2] - nm1);
            float p3 = __expf(c[nt][3] - nm1);
            rs0 += p0 + p1; rs1 += p2 + p3;
            c[nt][0] = p0; c[nt][1] = p1; c[nt][2] = p2; c[nt][3] = p3;
        }
        rs0 += __shfl_xor_sync(0xffffffffu, rs0, 1);
        rs0 += __shfl_xor_sync(0xffffffffu, rs0, 2);
        rs1 += __shfl_xor_sync(0xffffffffu, rs1, 1);
        rs1 += __shfl_xor_sync(0xffffffffu, rs1, 2);
        l0r = l0r * sc0 + rs0;
        l1r = l1r * sc1 + rs1;

        // rescale O only if some lane's running max moved (x1.0 skip is exact)
        if (__ballot_sync(0xffffffffu, (sc0 != 1.f) || (sc1 != 1.f))) {
            #pragma unroll
            for (int nt = 0; nt < 16; nt++) {
                o[nt][0] *= sc0; o[nt][1] *= sc0;
                o[nt][2] *= sc1; o[nt][3] *= sc1;
            }
        }

        // ---- O-GEMM: O += P @ X (k = 64 kv rows); P split inline per s-step
        #pragma unroll
        for (int s = 0; s < 4; s++) {
            uint32_t aH[4], aL[4];
            split2(c[2 * s][0],     c[2 * s][1],     aH[0], aL[0]);
            split2(c[2 * s][2],     c[2 * s][3],     aH[1], aL[1]);
            split2(c[2 * s + 1][0], c[2 * s + 1][1], aH[2], aL[2]);
            split2(c[2 * s + 1][2], c[2 * s + 1][3], aH[3], aL[3]);
            #pragma unroll
            for (int np = 0; np < 8; np++) {
                int brow = s * 16 + rr + ((mat & 1) << 3);   // k = kv rows
                int bu   = 2 * np + (mat >> 1);              // n = f cols
                uint32_t baddr = xb + (uint32_t)brow * 256 + ((bu ^ (brow & 7)) << 4);
                uint32_t bh[4], bl[4];
                ldsm4t(bh, baddr);
                ldsm4t(bl, baddr + THB);
                mma16816(o[2 * np],     aH, &bh[0]);
                mma16816(o[2 * np],     aH, &bl[0]);
                mma16816(o[2 * np],     aL, &bh[0]);
                mma16816(o[2 * np + 1], aH, &bh[2]);
                mma16816(o[2 * np + 1], aH, &bl[2]);
                mma16816(o[2 * np + 1], aL, &bh[2]);
            }
        }
    }

    // ---- epilogue: normalize, +bias, elu, store
    const float inv0 = 1.f / l0r, inv1 = 1.f / l1r;
    const int gr0 = row0 + wrow0 + g;
    float* outb = out + (size_t)b * N_DIM * F_DIM;
    #pragma unroll
    for (int nt = 0; nt < 16; nt++) {
        int f = nt * 8 + 2 * t4;
        float bb0 = __ldg(&bias[f]), bb1 = __ldg(&bias[f + 1]);
        float v0 = o[nt][0] * inv0 + bb0; v0 = (v0 > 0.f) ? v0 : expm1f(v0);
        float v1 = o[nt][1] * inv0 + bb1; v1 = (v1 > 0.f) ? v1 : expm1f(v1);
        float v2 = o[nt][2] * inv1 + bb0; v2 = (v2 > 0.f) ? v2 : expm1f(v2);
        float v3 = o[nt][3] * inv1 + bb1; v3 = (v3 > 0.f) ? v3 : expm1f(v3);
        *reinterpret_cast<float2*>(&outb[(size_t)gr0 * F_DIM + f])       = make_float2(v0, v1);
        *reinterpret_cast<float2*>(&outb[(size_t)(gr0 + 8) * F_DIM + f]) = make_float2(v2, v3);
    }
}

// ---------------------------------------------------------------------------
// Launch. Inputs mapped by element count (all four unique):
//   x: 4194304 f32, adj: 67108864 i32, W_a: 16384 f32, bias: 128 f32
// ---------------------------------------------------------------------------
extern "C" void kernel_launch(void* const* d_in, const int* in_sizes, int n_in,
                              void* d_out, int out_size)
{
    (void)out_size;
    const float* x  = nullptr;
    const int*   aj = nullptr;
    const float* W  = nullptr;
    const float* bi = nullptr;
    for (int i = 0; i < n_in; i++) {
        switch (in_sizes[i]) {
            case (int)NELEM:    x  = (const float*)d_in[i]; break;  // 4194304
            case 67108864:      aj = (const int*)  d_in[i]; break;
            case F_DIM * F_DIM: W  = (const float*)d_in[i]; break;  // 16384
            case F_DIM:         bi = (const float*)d_in[i]; break;  // 128
            default: break;
        }
    }
    float* out = (float*)d_out;

    split_kernel<<<(int)(NELEM / 4 / 256), 256>>>(x, W);

    cudaFuncSetAttribute(gat_mma_kernel, cudaFuncAttributeMaxDynamicSharedMemorySize,
                         SM_TOTAL);
    dim3 grid(N_DIM / 64, B_DIM);   // (32, 16) = 512 blocks of 128 threads
    gat_mma_kernel<<<grid, 128, SM_TOTAL>>>(aj, bi, out);
}

// round 16
// speedup vs baseline: 1.0791x; 1.0791x over previous
#include <cuda_runtime.h>
#include <cuda_bf16.h>
#include <math.h>
#include <stdint.h>

// Fixed shapes: x[16,2048,128], adj[16,2048,2048], W[128,128], bias[1,128]
#define B_DIM 16
#define N_DIM 2048
#define F_DIM 128
#define NEG_BIG (-9e15f)
#define LOG2E 1.44269504f
#define NELEM ((size_t)B_DIM * N_DIM * F_DIM)   // 4194304

// ---------------- device scratch (no allocation allowed) -------------------
__device__ __align__(256) __nv_bfloat16 g_x_h [NELEM];
__device__ __align__(256) __nv_bfloat16 g_x_l [NELEM];
__device__ __align__(256) __nv_bfloat16 g_wt_h[F_DIM * F_DIM];   // W^T [g][f]
__device__ __align__(256) __nv_bfloat16 g_wt_l[F_DIM * F_DIM];

// ---------------- PTX helpers (sm_80+ features only) ------------------------
__device__ __forceinline__ uint32_t smem_u32(const void* p) {
    uint32_t a;
    asm("{ .reg .u64 t; cvta.to.shared.u64 t, %1; cvt.u32.u64 %0, t; }"
        : "=r"(a) : "l"(p));
    return a;
}
__device__ __forceinline__ void cp16(uint32_t saddr, const void* gaddr) {
    asm volatile("cp.async.cg.shared.global [%0], [%1], 16;"
                 :: "r"(saddr), "l"(gaddr));
}
#define CP_COMMIT() asm volatile("cp.async.commit_group;" ::: "memory")
#define CP_WAIT1()  asm volatile("cp.async.wait_group 1;"  ::: "memory")
#define CP_WAIT0()  asm volatile("cp.async.wait_group 0;"  ::: "memory")

__device__ __forceinline__ void ldsm4(uint32_t* r, uint32_t addr) {
    asm volatile("ldmatrix.sync.aligned.m8n8.x4.shared.b16 {%0,%1,%2,%3}, [%4];"
                 : "=r"(r[0]), "=r"(r[1]), "=r"(r[2]), "=r"(r[3]) : "r"(addr));
}
__device__ __forceinline__ void ldsm4t(uint32_t* r, uint32_t addr) {
    asm volatile("ldmatrix.sync.aligned.m8n8.x4.trans.shared.b16 {%0,%1,%2,%3}, [%4];"
                 : "=r"(r[0]), "=r"(r[1]), "=r"(r[2]), "=r"(r[3]) : "r"(addr));
}
// D += A*B  (m16n8k16, row.col, bf16 in, f32 accum)
__device__ __forceinline__ void mma16816(float* d, const uint32_t* a, const uint32_t* b) {
    asm volatile("mma.sync.aligned.m16n8k16.row.col.f32.bf16.bf16.f32 "
        "{%0,%1,%2,%3}, {%4,%5,%6,%7}, {%8,%9}, {%0,%1,%2,%3};"
        : "+f"(d[0]), "+f"(d[1]), "+f"(d[2]), "+f"(d[3])
        : "r"(a[0]), "r"(a[1]), "r"(a[2]), "r"(a[3]), "r"(b[0]), "r"(b[1]));
}

// bare exp2 (logits pre-scaled by LOG2E -> this IS exp of unscaled diffs)
__device__ __forceinline__ float ex2f(float x) {
    float r;
    asm("ex2.approx.ftz.f32 %0, %1;" : "=f"(r) : "f"(x));
    return r;
}

// packed bf16 hi/lo split of a float pair
__device__ __forceinline__ void split2(float a, float b, uint32_t& hi, uint32_t& lo) {
    uint32_t h;
    asm("cvt.rn.bf16x2.f32 %0, %1, %2;" : "=r"(h) : "f"(b), "f"(a));
    float ha = __uint_as_float(h << 16);
    float hb = __uint_as_float(h & 0xffff0000u);
    float la = a - ha, lb = b - hb;
    uint32_t l;
    asm("cvt.rn.bf16x2.f32 %0, %1, %2;" : "=r"(l) : "f"(lb), "f"(la));
    hi = h; lo = l;
}

// ---------------- SMEM layout (96KB total -> 2 blocks/SM) -------------------
// regions: 64 rows x 128 bf16 = 16KB; hi at +0, lo at +THB within a region.
// row = 256B = 16x 16B units, unit swizzle u ^= (row & 7).
#define THB      16384
#define SM_XW    0                           // 32KB: xw hi/lo (prologue: x rows)
#define SM_XB(buf) (32768 + (buf) * 32768)   // 2 x 32KB x-tile buffers
#define SM_TOTAL 98304

// ---------------------------------------------------------------------------
// Fused prep: x bf16 hi/lo split; first 16 blocks also split W^T.
// ---------------------------------------------------------------------------
__global__ void __launch_bounds__(256) split_kernel(const float* __restrict__ x,
                                                    const float* __restrict__ W)
{
    size_t i4 = (size_t)blockIdx.x * 256 + threadIdx.x;
    float4 v = *reinterpret_cast<const float4*>(x + i4 * 4);
    uint2 h, l;
    split2(v.x, v.y, h.x, l.x);
    split2(v.z, v.w, h.y, l.y);
    reinterpret_cast<uint2*>(g_x_h)[i4] = h;
    reinterpret_cast<uint2*>(g_x_l)[i4] = l;

    if (blockIdx.x < 16) {
        int idx0 = (blockIdx.x * 256 + threadIdx.x) * 4;
        #pragma unroll
        for (int k = 0; k < 4; k++) {
            int idx = idx0 + k;                    // 0..16383
            int gg = idx >> 7, f = idx & 127;
            float wv = W[f * F_DIM + gg];
            __nv_bfloat16 hh = __float2bfloat16(wv);
            __nv_bfloat16 ll = __float2bfloat16(wv - __bfloat162float(hh));
            g_wt_h[idx] = hh;                      // [g][f] row-major
            g_wt_l[idx] = ll;
        }
    }
}

// ---------------------------------------------------------------------------
// Main fused kernel (R13 structure = best: 338.2us). Block = 64-row tile,
// 4 warps, 64-col kv tiles (32 iterations), 2 blocks/SM. Logits carry a
// LOG2E scale folded into xw at the prologue; all exps are bare ex2.
// ---------------------------------------------------------------------------
__global__ void __launch_bounds__(128, 2) gat_mma_kernel(
    const int*   __restrict__ adj,
    const float* __restrict__ bias,
    float*       __restrict__ out)
{
    extern __shared__ char sm[];
    const uint32_t sb = smem_u32(sm);

    const int b    = blockIdx.y;
    const int row0 = blockIdx.x * 64;
    const int tid  = threadIdx.x;
    const int lane = tid & 31;
    const int w    = tid >> 5;         // 0..3
    const int g    = lane >> 2;        // mma group row
    const int t4   = lane & 3;         // mma group col
    const int wrow0 = w * 16;          // warp's row base within 64-row tile
    const int mat  = lane >> 3;        // ldmatrix lane roles
    const int rr   = lane & 7;

    const char* xh_g  = (const char*)(g_x_h + (size_t)b * N_DIM * F_DIM);
    const char* xl_g  = (const char*)(g_x_l + (size_t)b * N_DIM * F_DIM);
    const char* xh_r0 = xh_g + (size_t)row0 * 256;   // this block's own rows
    const char* xl_r0 = xl_g + (size_t)row0 * 256;
    const int*  adjb  = adj + (size_t)b * N_DIM * N_DIM + (size_t)row0 * N_DIM;

    // ======== prologue: compute xw tile (64 rows) via HMMA ========
    // x rows (A) -> SM_XW region; W^T (B, 128 rows) -> XB(0)+XB(1)
    #pragma unroll
    for (int k = 0; k < 8; k++) {              // 64 rows x 16 units
        int uu  = k * 128 + tid;
        int row = uu >> 4, u = uu & 15;
        uint32_t so = (uint32_t)row * 256 + ((u ^ (row & 7)) << 4);
        size_t   go = (size_t)row * 256 + u * 16;
        cp16(sb + SM_XW + so,       xh_r0 + go);
        cp16(sb + SM_XW + THB + so, xl_r0 + go);
    }
    #pragma unroll
    for (int k = 0; k < 16; k++) {             // 128 Wt rows x 16 units
        int uu  = k * 128 + tid;
        int row = uu >> 4, u = uu & 15;
        uint32_t so = SM_XB(row >> 6) + (uint32_t)(row & 63) * 256
                    + (((u ^ (row & 7))) << 4);
        size_t   go = (size_t)row * 256 + u * 16;
        cp16(sb + so,       (const char*)g_wt_h + go);
        cp16(sb + so + THB, (const char*)g_wt_l + go);
    }
    CP_COMMIT();
    CP_WAIT0();
    __syncthreads();

    {
        float cw[16][4];
        #pragma unroll
        for (int nt = 0; nt < 16; nt++)
            #pragma unroll
            for (int q = 0; q < 4; q++) cw[nt][q] = 0.f;

        #pragma unroll
        for (int s = 0; s < 8; s++) {
            int arow = wrow0 + rr + ((mat & 1) << 3);
            int au   = 2 * s + (mat >> 1);
            uint32_t aaddr = sb + SM_XW + (uint32_t)arow * 256 + ((au ^ (arow & 7)) << 4);
            uint32_t ah[4], al[4];
            ldsm4(ah, aaddr);
            ldsm4(al, aaddr + THB);
            #pragma unroll
            for (int np = 0; np < 16; np += 2) {
                int bu = 2 * s + (mat & 1);
                int br = np * 8 + rr + ((mat >> 1) << 3);
                uint32_t ba = sb + SM_XB(br >> 6) + (uint32_t)(br & 63) * 256
                            + ((bu ^ (br & 7)) << 4);
                uint32_t bh[4], bl[4];
                ldsm4(bh, ba);
                ldsm4(bl, ba + THB);
                mma16816(cw[np],     ah, &bh[0]);
                mma16816(cw[np],     ah, &bl[0]);
                mma16816(cw[np],     al, &bh[0]);
                mma16816(cw[np + 1], ah, &bh[2]);
                mma16816(cw[np + 1], ah, &bl[2]);
                mma16816(cw[np + 1], al, &bh[2]);
            }
        }

        __syncthreads();      // all reads of SM_XW (x rows) complete
        // fold LOG2E into xw, split C-frags -> xw hi/lo smem tiles
        const int r0a = wrow0 + g, r1a = r0a + 8;
        #pragma unroll
        for (int nt = 0; nt < 16; nt++) {
            uint32_t h01, l01, h23, l23;
            split2(cw[nt][0] * LOG2E, cw[nt][1] * LOG2E, h01, l01);
            split2(cw[nt][2] * LOG2E, cw[nt][3] * LOG2E, h23, l23);
            uint32_t off0 = (uint32_t)r0a * 256 + ((nt ^ (r0a & 7)) << 4) + 4 * t4;
            uint32_t off1 = (uint32_t)r1a * 256 + ((nt ^ (r1a & 7)) << 4) + 4 * t4;
            *reinterpret_cast<uint32_t*>(sm + SM_XW + off0) = h01;
            *reinterpret_cast<uint32_t*>(sm + SM_XW + THB + off0) = l01;
            *reinterpret_cast<uint32_t*>(sm + SM_XW + off1) = h23;
            *reinterpret_cast<uint32_t*>(sm + SM_XW + THB + off1) = l23;
        }
    }
    __syncthreads();          // xw visible; XB reads done everywhere

    // prefetch x kv-tile 0 into XB(0)
    #pragma unroll
    for (int k = 0; k < 8; k++) {
        int uu  = k * 128 + tid;
        int row = uu >> 4, u = uu & 15;
        uint32_t so = (uint32_t)row * 256 + ((u ^ (row & 7)) << 4);
        size_t   go = (size_t)row * 256 + u * 16;
        cp16(sb + SM_XB(0) + so,       xh_g + go);
        cp16(sb + SM_XB(0) + THB + so, xl_g + go);
    }
    CP_COMMIT();

    float o[16][4];
    #pragma unroll
    for (int nt = 0; nt < 16; nt++)
        #pragma unroll
        for (int q = 0; q < 4; q++) o[nt][q] = 0.f;
    float m0r = -INFINITY, m1r = -INFINITY, l0r = 0.f, l1r = 0.f;

    for (int t = 0; t < 32; t++) {
        const int mbase = t * 64;

        // ---- batched adj prefetch: one int2 per row -> regs (64 cols)
        int2 ajv[16];
        #pragma unroll
        for (int rw = 0; rw < 16; rw++)
            ajv[rw] = *reinterpret_cast<const int2*>(
                &adjb[(size_t)(wrow0 + rw) * N_DIM + mbase + 2 * lane]);

        __syncthreads();               // buf (t+1)&1 readers (tile t-1) done
        if (t < 31) {                  // prefetch next x tile into buf^1
            const char* nh = xh_g + (size_t)(t + 1) * 64 * 256;
            const char* nl = xl_g + (size_t)(t + 1) * 64 * 256;
            uint32_t dst = sb + SM_XB((t + 1) & 1);
            #pragma unroll
            for (int k = 0; k < 8; k++) {
                int uu = k * 128 + tid;
                int row = uu >> 4, u = uu & 15;
                uint32_t so = (uint32_t)row * 256 + ((u ^ (row & 7)) << 4);
                size_t   go = (size_t)row * 256 + u * 16;
                cp16(dst + so,       nh + go);
                cp16(dst + THB + so, nl + go);
            }
            CP_COMMIT();
        }

        // ---- ballots: col = 2*lane + c; bit (col>>1)=lane of word c
        uint32_t wE0, wO0, wE1, wO1;
        #pragma unroll
        for (int rw = 0; rw < 16; rw++) {
            uint32_t b0 = __ballot_sync(0xffffffffu, ajv[rw].x > 0);
            uint32_t b1 = __ballot_sync(0xffffffffu, ajv[rw].y > 0);
            if (rw == g)     { wE0 = b0; wO0 = b1; }
            if (rw == g + 8) { wE1 = b0; wO1 = b1; }
        }

        if (t < 31) CP_WAIT1(); else CP_WAIT0();
        __syncthreads();               // current tile visible to all

        const uint32_t xb = sb + SM_XB(t & 1);   // x_h base; x_l = +THB

        // ---- S-GEMM: c[8][4] (16 rows x 64 cols), 3 bf16 terms, k = f (128)
        float c[8][4];
        #pragma unroll
        for (int nt = 0; nt < 8; nt++)
            #pragma unroll
            for (int q = 0; q < 4; q++) c[nt][q] = 0.f;

        #pragma unroll
        for (int s = 0; s < 8; s++) {
            int arow = wrow0 + rr + ((mat & 1) << 3);
            int au   = 2 * s + (mat >> 1);
            uint32_t aaddr = sb + SM_XW + (uint32_t)arow * 256 + ((au ^ (arow & 7)) << 4);
            uint32_t ah[4], al[4];
            ldsm4(ah, aaddr);
            ldsm4(al, aaddr + THB);
            #pragma unroll
            for (int np = 0; np < 4; np++) {
                int brow = np * 16 + rr + ((mat >> 1) << 3);
                int bu   = 2 * s + (mat & 1);
                uint32_t baddr = xb + (uint32_t)brow * 256 + ((bu ^ (brow & 7)) << 4);
                uint32_t bh[4], bl[4];
                ldsm4(bh, baddr);
                ldsm4(bl, baddr + THB);
                mma16816(c[2 * np],     ah, &bh[0]);
                mma16816(c[2 * np],     ah, &bl[0]);
                mma16816(c[2 * np],     al, &bh[0]);
                mma16816(c[2 * np + 1], ah, &bh[2]);
                mma16816(c[2 * np + 1], ah, &bl[2]);
                mma16816(c[2 * np + 1], al, &bh[2]);
            }
        }

        // ---- leakyrelu + mask + online softmax (rows g / g+8), exp2 domain
        float rmax0 = -INFINITY, rmax1 = -INFINITY;
        #pragma unroll
        for (int nt = 0; nt < 8; nt++) {
            int ln = 4 * nt + t4;      // bit index: col>>1 with col = nt*8+2*t4
            float e;
            e = fmaxf(c[nt][0], 0.1f * c[nt][0]);
            e = ((wE0 >> ln) & 1u) ? e : NEG_BIG; c[nt][0] = e; rmax0 = fmaxf(rmax0, e);
            e = fmaxf(c[nt][1], 0.1f * c[nt][1]);
            e = ((wO0 >> ln) & 1u) ? e : NEG_BIG; c[nt][1] = e; rmax0 = fmaxf(rmax0, e);
            e = fmaxf(c[nt][2], 0.1f * c[nt][2]);
            e = ((wE1 >> ln) & 1u) ? e : NEG_BIG; c[nt][2] = e; rmax1 = fmaxf(rmax1, e);
            e = fmaxf(c[nt][3], 0.1f * c[nt][3]);
            e = ((wO1 >> ln) & 1u) ? e : NEG_BIG; c[nt][3] = e; rmax1 = fmaxf(rmax1, e);
        }
        rmax0 = fmaxf(rmax0, __shfl_xor_sync(0xffffffffu, rmax0, 1));
        rmax0 = fmaxf(rmax0, __shfl_xor_sync(0xffffffffu, rmax0, 2));
        rmax1 = fmaxf(rmax1, __shfl_xor_sync(0xffffffffu, rmax1, 1));
        rmax1 = fmaxf(rmax1, __shfl_xor_sync(0xffffffffu, rmax1, 2));

        float nm0 = fmaxf(m0r, rmax0), nm1 = fmaxf(m1r, rmax1);
        float sc0 = (nm0 == -INFINITY) ? 0.f : ex2f(m0r - nm0);
        float sc1 = (nm1 == -INFINITY) ? 0.f : ex2f(m1r - nm1);
        m0r = nm0; m1r = nm1;

        float rs0 = 0.f, rs1 = 0.f;
        #pragma unroll
        for (int nt = 0; nt < 8; nt++) {         // c becomes P in place
            float p0 = ex2f(c[nt][0] - nm0);     // masked NEG_BIG -> 0 (ftz)
            float p1 = ex2f(c[nt][1] - nm0);
            float p2 = ex2f(c[nt][2] - nm1);
            float p3 = ex2f(c[nt][3] - nm1);
            rs0 += p0 + p1; rs1 += p2 + p3;
            c[nt][0] = p0; c[nt][1] = p1; c[nt][2] = p2; c[nt][3] = p3;
        }
        rs0 += __shfl_xor_sync(0xffffffffu, rs0, 1);
        rs0 += __shfl_xor_sync(0xffffffffu, rs0, 2);
        rs1 += __shfl_xor_sync(0xffffffffu, rs1, 1);
        rs1 += __shfl_xor_sync(0xffffffffu, rs1, 2);
        l0r = l0r * sc0 + rs0;
        l1r = l1r * sc1 + rs1;

        // rescale O only if some lane's running max moved (x1.0 skip is exact)
        if (__ballot_sync(0xffffffffu, (sc0 != 1.f) || (sc1 != 1.f))) {
            #pragma unroll
            for (int nt = 0; nt < 16; nt++) {
                o[nt][0] *= sc0; o[nt][1] *= sc0;
                o[nt][2] *= sc1; o[nt][3] *= sc1;
            }
        }

        // ---- O-GEMM: O += P @ X (k = 64 kv rows); P split inline per s-step
        #pragma unroll
        for (int s = 0; s < 4; s++) {
            uint32_t aH[4], aL[4];
            split2(c[2 * s][0],     c[2 * s][1],     aH[0], aL[0]);
            split2(c[2 * s][2],     c[2 * s][3],     aH[1], aL[1]);
            split2(c[2 * s + 1][0], c[2 * s + 1][1], aH[2], aL[2]);
            split2(c[2 * s + 1][2], c[2 * s + 1][3], aH[3], aL[3]);
            #pragma unroll
            for (int np = 0; np < 8; np++) {
                int brow = s * 16 + rr + ((mat & 1) << 3);   // k = kv rows
                int bu   = 2 * np + (mat >> 1);              // n = f cols
                uint32_t baddr = xb + (uint32_t)brow * 256 + ((bu ^ (brow & 7)) << 4);
                uint32_t bh[4], bl[4];
                ldsm4t(bh, baddr);
                ldsm4t(bl, baddr + THB);
                mma16816(o[2 * np],     aH, &bh[0]);
                mma16816(o[2 * np],     aH, &bl[0]);
                mma16816(o[2 * np],     aL, &bh[0]);
                mma16816(o[2 * np + 1], aH, &bh[2]);
                mma16816(o[2 * np + 1], aH, &bl[2]);
                mma16816(o[2 * np + 1], aL, &bh[2]);
            }
        }
    }

    // ---- epilogue: normalize, +bias, elu, store
    const float inv0 = 1.f / l0r, inv1 = 1.f / l1r;
    const int gr0 = row0 + wrow0 + g;
    float* outb = out + (size_t)b * N_DIM * F_DIM;
    #pragma unroll
    for (int nt = 0; nt < 16; nt++) {
        int f = nt * 8 + 2 * t4;
        float bb0 = __ldg(&bias[f]), bb1 = __ldg(&bias[f + 1]);
        float v0 = o[nt][0] * inv0 + bb0; v0 = (v0 > 0.f) ? v0 : expm1f(v0);
        float v1 = o[nt][1] * inv0 + bb1; v1 = (v1 > 0.f) ? v1 : expm1f(v1);
        float v2 = o[nt][2] * inv1 + bb0; v2 = (v2 > 0.f) ? v2 : expm1f(v2);
        float v3 = o[nt][3] * inv1 + bb1; v3 = (v3 > 0.f) ? v3 : expm1f(v3);
        *reinterpret_cast<float2*>(&outb[(size_t)gr0 * F_DIM + f])       = make_float2(v0, v1);
        *reinterpret_cast<float2*>(&outb[(size_t)(gr0 + 8) * F_DIM + f]) = make_float2(v2, v3);
    }
}

// ---------------------------------------------------------------------------
// Launch. Inputs mapped by element count (all four unique):
//   x: 4194304 f32, adj: 67108864 i32, W_a: 16384 f32, bias: 128 f32
// ---------------------------------------------------------------------------
extern "C" void kernel_launch(void* const* d_in, const int* in_sizes, int n_in,
                              void* d_out, int out_size)
{
    (void)out_size;
    const float* x  = nullptr;
    const int*   aj = nullptr;
    const float* W  = nullptr;
    const float* bi = nullptr;
    for (int i = 0; i < n_in; i++) {
        switch (in_sizes[i]) {
            case (int)NELEM:    x  = (const float*)d_in[i]; break;  // 4194304
            case 67108864:      aj = (const int*)  d_in[i]; break;
            case F_DIM * F_DIM: W  = (const float*)d_in[i]; break;  // 16384
            case F_DIM:         bi = (const float*)d_in[i]; break;  // 128
            default: break;
        }
    }
    float* out = (float*)d_out;

    split_kernel<<<(int)(NELEM / 4 / 256), 256>>>(x, W);

    cudaFuncSetAttribute(gat_mma_kernel, cudaFuncAttributeMaxDynamicSharedMemorySize,
                         SM_TOTAL);
    dim3 grid(N_DIM / 64, B_DIM);   // (32, 16) = 512 blocks of 128 threads
    gat_mma_kernel<<<grid, 128, SM_TOTAL>>>(aj, bi, out);
}